// round 5
// baseline (speedup 1.0000x reference)
#include <cuda_runtime.h>
#include <cuda_bf16.h>
#include <mma.h>
#include <type_traits>

using namespace nvcuda;
typedef __nv_bfloat16 bf16;

#define Bb 2
#define Ss 2048
#define Nn 4096
#define Dd 1024
#define Vv 32000
#define NLAYERS 6
#define LN_EPS 1e-5f
#define BSROWS (Bb * Ss) /* 4096 */

// ---------------- scratch (static device globals; no allocation) ----------
__device__ __align__(16) bf16 g_v_hi[BSROWS * Dd], g_v_lo[BSROWS * Dd];
__device__ __align__(16) bf16 g_x_hi[BSROWS * Nn], g_x_lo[BSROWS * Nn];
__device__ __align__(16) bf16 g_kv_hi[Bb * Nn * Dd], g_kv_lo[Bb * Nn * Dd];
__device__ __align__(16) bf16 g_a_hi[BSROWS * Dd], g_a_lo[BSROWS * Dd];
__device__ __align__(16) bf16 g_y_hi[BSROWS * Nn], g_y_lo[BSROWS * Nn];
__device__ __align__(16) float g_t[BSROWS * Dd];
__device__ __align__(16) bf16 g_Dx_hi[Dd * Nn], g_Dx_lo[Dd * Nn];
__device__ __align__(16) bf16 g_Dy_hi[Dd * Nn], g_Dy_lo[Dd * Nn];
__device__ __align__(16) bf16 g_E_hi[Nn * Dd], g_E_lo[Nn * Dd];
__device__ __align__(16) bf16 g_R_hi[(size_t)Dd * Vv], g_R_lo[(size_t)Dd * Vv];

__device__ __forceinline__ void bsplit(float f, bf16& h, bf16& l) {
    h = __float2bfloat16(f);
    l = __float2bfloat16(f - __bfloat162float(h));
}

// ---------------- weight split (fp32 -> bf16 hi/lo), 8 elems/thread -------
__global__ void split_kernel(const float* __restrict__ w,
                             bf16* __restrict__ hi, bf16* __restrict__ lo) {
    size_t i = (size_t)blockIdx.x * blockDim.x + threadIdx.x;
    float4 s0 = ((const float4*)w)[2 * i];
    float4 s1 = ((const float4*)w)[2 * i + 1];
    bf16 h[8], l[8];
    bsplit(s0.x, h[0], l[0]); bsplit(s0.y, h[1], l[1]);
    bsplit(s0.z, h[2], l[2]); bsplit(s0.w, h[3], l[3]);
    bsplit(s1.x, h[4], l[4]); bsplit(s1.y, h[5], l[5]);
    bsplit(s1.z, h[6], l[6]); bsplit(s1.w, h[7], l[7]);
    ((uint4*)hi)[i] = *(uint4*)h;
    ((uint4*)lo)[i] = *(uint4*)l;
}

// ---------------- embedding gather + split --------------------------------
__global__ void gather_kernel(const int* __restrict__ idx,
                              const float* __restrict__ emb,
                              bf16* __restrict__ vhi, bf16* __restrict__ vlo) {
    int row = blockIdx.x;
    int t = threadIdx.x;  // 256 threads, 4 elems each
    float4 s = ((const float4*)(emb + (size_t)idx[row] * Dd))[t];
    bf16 h[4], l[4];
    bsplit(s.x, h[0], l[0]); bsplit(s.y, h[1], l[1]);
    bsplit(s.z, h[2], l[2]); bsplit(s.w, h[3], l[3]);
    ((uint2*)(vhi + (size_t)row * Dd))[t] = *(uint2*)h;
    ((uint2*)(vlo + (size_t)row * Dd))[t] = *(uint2*)l;
}

// ---------------- fused v = LN(v + LN(t)), bf16 hi/lo state ----------------
__device__ __forceinline__ void block_reduce2(float& s, float& s2, float* sh) {
#pragma unroll
    for (int o = 16; o > 0; o >>= 1) {
        s += __shfl_down_sync(0xFFFFFFFFu, s, o);
        s2 += __shfl_down_sync(0xFFFFFFFFu, s2, o);
    }
    int warp = threadIdx.x >> 5, lane = threadIdx.x & 31;
    if (lane == 0) { sh[warp * 2] = s; sh[warp * 2 + 1] = s2; }
    __syncthreads();
    float ts = 0.f, ts2 = 0.f;
#pragma unroll
    for (int w = 0; w < 8; w++) { ts += sh[w * 2]; ts2 += sh[w * 2 + 1]; }
    s = ts; s2 = ts2;
    __syncthreads();
}

__global__ void ln_res_ln_kernel(bf16* __restrict__ vhi, bf16* __restrict__ vlo,
                                 const float* __restrict__ t) {
    __shared__ float sh[16];
    int row = blockIdx.x;
    int tid = threadIdx.x;
    const float4 tv = ((const float4*)(t + (size_t)row * Dd))[tid];
    uint2 vhu = ((const uint2*)(vhi + (size_t)row * Dd))[tid];
    uint2 vlu = ((const uint2*)(vlo + (size_t)row * Dd))[tid];
    const bf16* vhp = (const bf16*)&vhu;
    const bf16* vlp = (const bf16*)&vlu;

    float s = tv.x + tv.y + tv.z + tv.w;
    float s2 = tv.x * tv.x + tv.y * tv.y + tv.z * tv.z + tv.w * tv.w;
    block_reduce2(s, s2, sh);
    float m = s * (1.0f / Dd);
    float inv = rsqrtf(s2 * (1.0f / Dd) - m * m + LN_EPS);

    float u[4];
    u[0] = (__bfloat162float(vhp[0]) + __bfloat162float(vlp[0])) + (tv.x - m) * inv;
    u[1] = (__bfloat162float(vhp[1]) + __bfloat162float(vlp[1])) + (tv.y - m) * inv;
    u[2] = (__bfloat162float(vhp[2]) + __bfloat162float(vlp[2])) + (tv.z - m) * inv;
    u[3] = (__bfloat162float(vhp[3]) + __bfloat162float(vlp[3])) + (tv.w - m) * inv;

    s = u[0] + u[1] + u[2] + u[3];
    s2 = u[0] * u[0] + u[1] * u[1] + u[2] * u[2] + u[3] * u[3];
    block_reduce2(s, s2, sh);
    m = s * (1.0f / Dd);
    inv = rsqrtf(s2 * (1.0f / Dd) - m * m + LN_EPS);

    bf16 h[4], l[4];
#pragma unroll
    for (int q = 0; q < 4; q++) bsplit((u[q] - m) * inv, h[q], l[q]);
    ((uint2*)(vhi + (size_t)row * Dd))[tid] = *(uint2*)h;
    ((uint2*)(vlo + (size_t)row * Dd))[tid] = *(uint2*)l;
}

// ---------------- cp.async helpers ----------------------------------------
__device__ __forceinline__ void cpa16(bf16* s, const bf16* g) {
    asm volatile("cp.async.cg.shared.global [%0],[%1],16;\n" ::
                 "r"((unsigned)__cvta_generic_to_shared(s)), "l"(g));
}
__device__ __forceinline__ void cpa_commit() {
    asm volatile("cp.async.commit_group;\n");
}

// ---------------- 3xBF16 split GEMM ----------------------------------------
// C = op(A) @ B where A,B are bf16 (hi,lo) pairs; acc fp32; 3 MMA terms:
// AhiBhi + AhiBlo + AloBhi.  TRANSA=1: A stored [K,M] row-major.
// EPI: 0 none, 1 relu, 2 relu*(AuxHi+AuxLo).  WLO: write bf16 hi/lo else fp32.
constexpr int BM = 128, BN = 64, BK = 32;
enum { EPI_NONE = 0, EPI_RELU = 1, EPI_RELU_MUL = 2 };

constexpr int LDA_NT = BK + 8;    // 40 bf16
constexpr int LDA_T  = BM + 8;    // 136
constexpr int LDBs   = BN + 8;    // 72
constexpr int SA_NT = BM * LDA_NT;  // 5120 elems
constexpr int SA_T  = BK * LDA_T;   // 4352
constexpr int SBn   = BK * LDBs;    // 2304

constexpr int SMEM_NT_BYTES = 2 * (2 * SA_NT + 2 * SBn) * 2;  // 59392
constexpr int SMEM_T_BYTES  = 2 * (2 * SA_T + 2 * SBn) * 2;   // 53248

template <bool TRANSA, int EPI, bool WLO>
__global__ void __launch_bounds__(256, 2)
gemm_bf16x3(const bf16* __restrict__ Ahi, const bf16* __restrict__ Alo,
            const bf16* __restrict__ Bhi, const bf16* __restrict__ Blo,
            float* __restrict__ Cf, bf16* __restrict__ Chi, bf16* __restrict__ Clo,
            const bf16* __restrict__ AuxHi, const bf16* __restrict__ AuxLo,
            int M, int Ncol, int K, long sA, long sB, long sC) {
    extern __shared__ bf16 smem[];
    constexpr int SA = TRANSA ? SA_T : SA_NT;
    constexpr int STAGE = 2 * SA + 2 * SBn;

    const int bz = blockIdx.z;
    Ahi += (long)bz * sA;
    Alo += (long)bz * sA;
    Bhi += (long)bz * sB;
    Blo += (long)bz * sB;

    const int rowBase = blockIdx.y * BM;
    const int colBase = blockIdx.x * BN;
    const int tid = threadIdx.x;
    const int warpId = tid >> 5;
    const int lane = tid & 31;
    const int wr = warpId >> 1;  // 0..3
    const int wc = warpId & 1;   // 0..1

    const int lda = TRANSA ? M : K;
    const int ldb = Ncol;
    const int ldc = Ncol;

    // global->smem index split
    const int arow = tid >> 1;          // NT: 0..127
    const int acol = (tid & 1) * 16;    // NT: 0 or 16
    const int tkr = tid >> 3;           // T: 0..31
    const int tmc = (tid & 7) * 16;     // T: 0..112
    const int brow = tid >> 3;          // 0..31
    const int bcol = (tid & 7) * 8;     // 0..56

    auto loadStage = [&](int s, int kBase) {
        bf16* aH = smem + s * STAGE;
        bf16* aL = aH + SA;
        bf16* bH = aL + SA;
        bf16* bL = bH + SBn;
        if constexpr (!TRANSA) {
            const bf16* gh = Ahi + (long)(rowBase + arow) * lda + kBase + acol;
            const bf16* gl = Alo + (long)(rowBase + arow) * lda + kBase + acol;
            cpa16(aH + arow * LDA_NT + acol, gh);
            cpa16(aH + arow * LDA_NT + acol + 8, gh + 8);
            cpa16(aL + arow * LDA_NT + acol, gl);
            cpa16(aL + arow * LDA_NT + acol + 8, gl + 8);
        } else {
            const bf16* gh = Ahi + (long)(kBase + tkr) * lda + rowBase + tmc;
            const bf16* gl = Alo + (long)(kBase + tkr) * lda + rowBase + tmc;
            cpa16(aH + tkr * LDA_T + tmc, gh);
            cpa16(aH + tkr * LDA_T + tmc + 8, gh + 8);
            cpa16(aL + tkr * LDA_T + tmc, gl);
            cpa16(aL + tkr * LDA_T + tmc + 8, gl + 8);
        }
        cpa16(bH + brow * LDBs + bcol, Bhi + (long)(kBase + brow) * ldb + colBase + bcol);
        cpa16(bL + brow * LDBs + bcol, Blo + (long)(kBase + brow) * ldb + colBase + bcol);
    };

    using ALayout = typename std::conditional<TRANSA, wmma::col_major, wmma::row_major>::type;
    using AFrag = wmma::fragment<wmma::matrix_a, 16, 16, 16, bf16, ALayout>;
    using BFrag = wmma::fragment<wmma::matrix_b, 16, 16, 16, bf16, wmma::row_major>;
    using CFrag = wmma::fragment<wmma::accumulator, 16, 16, 16, float>;

    CFrag acc[2][2];
#pragma unroll
    for (int i = 0; i < 2; i++)
#pragma unroll
        for (int j = 0; j < 2; j++) wmma::fill_fragment(acc[i][j], 0.0f);

    const int KT = K / BK;

    loadStage(0, 0);
    cpa_commit();

    for (int kt = 0; kt < KT; kt++) {
        const int cur = kt & 1;
        if (kt + 1 < KT) {
            loadStage(cur ^ 1, (kt + 1) * BK);
            cpa_commit();
            asm volatile("cp.async.wait_group 1;\n");
        } else {
            asm volatile("cp.async.wait_group 0;\n");
        }
        __syncthreads();

        const bf16* aH = smem + cur * STAGE;
        const bf16* aL = aH + SA;
        const bf16* bH = aL + SA;
        const bf16* bL = bH + SBn;

#pragma unroll
        for (int kk = 0; kk < BK / 16; kk++) {
            AFrag afh[2], afl[2];
            BFrag bfh[2], bfl[2];
#pragma unroll
            for (int i = 0; i < 2; i++) {
                if constexpr (!TRANSA) {
                    wmma::load_matrix_sync(afh[i], aH + (wr * 32 + i * 16) * LDA_NT + kk * 16, LDA_NT);
                    wmma::load_matrix_sync(afl[i], aL + (wr * 32 + i * 16) * LDA_NT + kk * 16, LDA_NT);
                } else {
                    wmma::load_matrix_sync(afh[i], aH + (kk * 16) * LDA_T + wr * 32 + i * 16, LDA_T);
                    wmma::load_matrix_sync(afl[i], aL + (kk * 16) * LDA_T + wr * 32 + i * 16, LDA_T);
                }
            }
#pragma unroll
            for (int j = 0; j < 2; j++) {
                wmma::load_matrix_sync(bfh[j], bH + (kk * 16) * LDBs + wc * 32 + j * 16, LDBs);
                wmma::load_matrix_sync(bfl[j], bL + (kk * 16) * LDBs + wc * 32 + j * 16, LDBs);
            }
#pragma unroll
            for (int i = 0; i < 2; i++)
#pragma unroll
                for (int j = 0; j < 2; j++) {
                    wmma::mma_sync(acc[i][j], afh[i], bfl[j], acc[i][j]);
                    wmma::mma_sync(acc[i][j], afl[i], bfh[j], acc[i][j]);
                    wmma::mma_sync(acc[i][j], afh[i], bfh[j], acc[i][j]);
                }
        }
        __syncthreads();
    }

    // ------------- epilogue (patch through smem; smem free after loop) -----
    float* patch = (float*)smem + warpId * 16 * 20;
    const int rr = lane >> 1;
    const int cc = (lane & 1) * 8;
#pragma unroll
    for (int i = 0; i < 2; i++)
#pragma unroll
        for (int j = 0; j < 2; j++) {
            wmma::store_matrix_sync(patch, acc[i][j], 20, wmma::mem_row_major);
            __syncwarp();
            long gr = rowBase + wr * 32 + i * 16 + rr;
            long gc = colBase + wc * 32 + j * 16 + cc;
            float vals[8];
#pragma unroll
            for (int q = 0; q < 8; q++) vals[q] = patch[rr * 20 + cc + q];
            if constexpr (EPI == EPI_RELU) {
#pragma unroll
                for (int q = 0; q < 8; q++) vals[q] = fmaxf(vals[q], 0.0f);
            } else if constexpr (EPI == EPI_RELU_MUL) {
                uint4 xhu = *(const uint4*)(AuxHi + gr * ldc + gc);
                uint4 xlu = *(const uint4*)(AuxLo + gr * ldc + gc);
                const bf16* xh = (const bf16*)&xhu;
                const bf16* xl = (const bf16*)&xlu;
#pragma unroll
                for (int q = 0; q < 8; q++)
                    vals[q] = fmaxf(vals[q], 0.0f) *
                              (__bfloat162float(xh[q]) + __bfloat162float(xl[q]));
            }
            if constexpr (WLO) {
                bf16 h[8], l[8];
#pragma unroll
                for (int q = 0; q < 8; q++) bsplit(vals[q], h[q], l[q]);
                *(uint4*)(Chi + (long)bz * sC + gr * ldc + gc) = *(uint4*)h;
                *(uint4*)(Clo + (long)bz * sC + gr * ldc + gc) = *(uint4*)l;
            } else {
                *(float4*)(Cf + (long)bz * sC + gr * ldc + gc) =
                    make_float4(vals[0], vals[1], vals[2], vals[3]);
                *(float4*)(Cf + (long)bz * sC + gr * ldc + gc + 4) =
                    make_float4(vals[4], vals[5], vals[6], vals[7]);
            }
            __syncwarp();
        }
}

// ---------------- launch -----------------------------------------------
extern "C" void kernel_launch(void* const* d_in, const int* in_sizes, int n_in,
                              void* d_out, int out_size) {
    const int* idx = (const int*)d_in[0];
    const float* emb = (const float*)d_in[1];
    const float* Dx = (const float*)d_in[2];
    const float* Dy = (const float*)d_in[3];
    const float* E = (const float*)d_in[4];
    const float* readout = (const float*)d_in[5];
    float* out = (float*)d_out;

    bf16 *vh, *vl, *xh, *xl, *kvh, *kvl, *ah, *al, *yh, *yl;
    bf16 *dxh, *dxl, *dyh, *dyl, *eh, *el, *rh, *rl;
    float* t;
    cudaGetSymbolAddress((void**)&vh, g_v_hi);
    cudaGetSymbolAddress((void**)&vl, g_v_lo);
    cudaGetSymbolAddress((void**)&xh, g_x_hi);
    cudaGetSymbolAddress((void**)&xl, g_x_lo);
    cudaGetSymbolAddress((void**)&kvh, g_kv_hi);
    cudaGetSymbolAddress((void**)&kvl, g_kv_lo);
    cudaGetSymbolAddress((void**)&ah, g_a_hi);
    cudaGetSymbolAddress((void**)&al, g_a_lo);
    cudaGetSymbolAddress((void**)&yh, g_y_hi);
    cudaGetSymbolAddress((void**)&yl, g_y_lo);
    cudaGetSymbolAddress((void**)&t, g_t);
    cudaGetSymbolAddress((void**)&dxh, g_Dx_hi);
    cudaGetSymbolAddress((void**)&dxl, g_Dx_lo);
    cudaGetSymbolAddress((void**)&dyh, g_Dy_hi);
    cudaGetSymbolAddress((void**)&dyl, g_Dy_lo);
    cudaGetSymbolAddress((void**)&eh, g_E_hi);
    cudaGetSymbolAddress((void**)&el, g_E_lo);
    cudaGetSymbolAddress((void**)&rh, g_R_hi);
    cudaGetSymbolAddress((void**)&rl, g_R_lo);

    cudaFuncSetAttribute(gemm_bf16x3<false, EPI_RELU, true>,
                         cudaFuncAttributeMaxDynamicSharedMemorySize, SMEM_NT_BYTES);
    cudaFuncSetAttribute(gemm_bf16x3<true, EPI_NONE, true>,
                         cudaFuncAttributeMaxDynamicSharedMemorySize, SMEM_T_BYTES);
    cudaFuncSetAttribute(gemm_bf16x3<false, EPI_NONE, true>,
                         cudaFuncAttributeMaxDynamicSharedMemorySize, SMEM_NT_BYTES);
    cudaFuncSetAttribute(gemm_bf16x3<false, EPI_RELU_MUL, true>,
                         cudaFuncAttributeMaxDynamicSharedMemorySize, SMEM_NT_BYTES);
    cudaFuncSetAttribute(gemm_bf16x3<false, EPI_NONE, false>,
                         cudaFuncAttributeMaxDynamicSharedMemorySize, SMEM_NT_BYTES);

    // split weights once per launch (deterministic)
    split_kernel<<<(Dd * Nn) / 2048, 256>>>(Dx, dxh, dxl);
    split_kernel<<<(Dd * Nn) / 2048, 256>>>(Dy, dyh, dyl);
    split_kernel<<<(Nn * Dd) / 2048, 256>>>(E, eh, el);
    split_kernel<<<(Dd * Vv) / 2048, 256>>>(readout, rh, rl);

    gather_kernel<<<BSROWS, 256>>>(idx, emb, vh, vl);

    for (int l = 0; l < NLAYERS; l++) {
        // x = relu(v @ Dx)
        gemm_bf16x3<false, EPI_RELU, true><<<dim3(Nn / BN, BSROWS / BM, 1), 256, SMEM_NT_BYTES>>>(
            vh, vl, dxh, dxl, nullptr, xh, xl, nullptr, nullptr, BSROWS, Nn, Dd, 0, 0, 0);

        // kv = x^T @ v per batch
        gemm_bf16x3<true, EPI_NONE, true><<<dim3(Dd / BN, Nn / BM, Bb), 256, SMEM_T_BYTES>>>(
            xh, xl, vh, vl, nullptr, kvh, kvl, nullptr, nullptr, Nn, Dd, Ss,
            (long)Ss * Nn, (long)Ss * Dd, (long)Nn * Dd);

        // a = x @ kv per batch
        gemm_bf16x3<false, EPI_NONE, true><<<dim3(Dd / BN, Ss / BM, Bb), 256, SMEM_NT_BYTES>>>(
            xh, xl, kvh, kvl, nullptr, ah, al, nullptr, nullptr, Ss, Dd, Nn,
            (long)Ss * Nn, (long)Nn * Dd, (long)Ss * Dd);

        // y = relu(a @ Dy) * x
        gemm_bf16x3<false, EPI_RELU_MUL, true><<<dim3(Nn / BN, BSROWS / BM, 1), 256, SMEM_NT_BYTES>>>(
            ah, al, dyh, dyl, nullptr, yh, yl, xh, xl, BSROWS, Nn, Dd, 0, 0, 0);

        // t = y @ E (fp32 out)
        gemm_bf16x3<false, EPI_NONE, false><<<dim3(Dd / BN, BSROWS / BM, 1), 256, SMEM_NT_BYTES>>>(
            yh, yl, eh, el, t, nullptr, nullptr, nullptr, nullptr, BSROWS, Dd, Nn, 0, 0, 0);

        // v = LN(v + LN(t))
        ln_res_ln_kernel<<<BSROWS, 256>>>(vh, vl, t);
    }

    // out = v @ readout (fp32 out, 3-term)
    gemm_bf16x3<false, EPI_NONE, false><<<dim3(Vv / BN, BSROWS / BM, 1), 256, SMEM_NT_BYTES>>>(
        vh, vl, rh, rl, out, nullptr, nullptr, nullptr, nullptr, BSROWS, Vv, Dd, 0, 0, 0);
}

// round 7
// speedup vs baseline: 1.2476x; 1.2476x over previous
#include <cuda_runtime.h>
#include <cuda_bf16.h>
#include <mma.h>
#include <type_traits>

using namespace nvcuda;
typedef __nv_bfloat16 bf16;

#define Bb 2
#define Ss 2048
#define Nn 4096
#define Dd 1024
#define Vv 32000
#define NLAYERS 6
#define LN_EPS 1e-5f
#define BSROWS (Bb * Ss)

// ---------------- scratch ---------------------------------------------------
__device__ __align__(16) bf16 g_v_hi[BSROWS * Dd], g_v_lo[BSROWS * Dd];
__device__ __align__(16) bf16 g_x_hi[(size_t)BSROWS * Nn], g_x_lo[(size_t)BSROWS * Nn];
__device__ __align__(16) bf16 g_kv_hi[Bb * Nn * Dd], g_kv_lo[Bb * Nn * Dd];
__device__ __align__(16) bf16 g_a_hi[BSROWS * Dd], g_a_lo[BSROWS * Dd];
__device__ __align__(16) bf16 g_y_hi[(size_t)BSROWS * Nn], g_y_lo[(size_t)BSROWS * Nn];
__device__ __align__(16) float g_t[BSROWS * Dd];
__device__ __align__(16) bf16 g_Dx_hi[(size_t)Dd * Nn], g_Dx_lo[(size_t)Dd * Nn];
__device__ __align__(16) bf16 g_Dy_hi[(size_t)Dd * Nn], g_Dy_lo[(size_t)Dd * Nn];
__device__ __align__(16) bf16 g_E_hi[(size_t)Nn * Dd], g_E_lo[(size_t)Nn * Dd];
__device__ __align__(16) bf16 g_R_hi[(size_t)Dd * Vv], g_R_lo[(size_t)Dd * Vv];

__device__ __forceinline__ void bsplit(float f, bf16& h, bf16& l) {
    h = __float2bfloat16(f);
    l = __float2bfloat16(f - __bfloat162float(h));
}

// ---------------- weight split ----------------------------------------------
__global__ void split_kernel(const float* __restrict__ w,
                             bf16* __restrict__ hi, bf16* __restrict__ lo) {
    size_t i = (size_t)blockIdx.x * blockDim.x + threadIdx.x;
    float4 s0 = ((const float4*)w)[2 * i];
    float4 s1 = ((const float4*)w)[2 * i + 1];
    bf16 h[8], l[8];
    bsplit(s0.x, h[0], l[0]); bsplit(s0.y, h[1], l[1]);
    bsplit(s0.z, h[2], l[2]); bsplit(s0.w, h[3], l[3]);
    bsplit(s1.x, h[4], l[4]); bsplit(s1.y, h[5], l[5]);
    bsplit(s1.z, h[6], l[6]); bsplit(s1.w, h[7], l[7]);
    ((uint4*)hi)[i] = *(uint4*)h;
    ((uint4*)lo)[i] = *(uint4*)l;
}

// ---------------- embedding gather + split ----------------------------------
__global__ void gather_kernel(const int* __restrict__ idx, const float* __restrict__ emb,
                              bf16* __restrict__ vhi, bf16* __restrict__ vlo) {
    int row = blockIdx.x;
    int t = threadIdx.x;
    float4 s = ((const float4*)(emb + (size_t)idx[row] * Dd))[t];
    bf16 h[4], l[4];
    bsplit(s.x, h[0], l[0]); bsplit(s.y, h[1], l[1]);
    bsplit(s.z, h[2], l[2]); bsplit(s.w, h[3], l[3]);
    ((uint2*)(vhi + (size_t)row * Dd))[t] = *(uint2*)h;
    ((uint2*)(vlo + (size_t)row * Dd))[t] = *(uint2*)l;
}

// ---------------- fused v = LN(v + LN(t)) ------------------------------------
__device__ __forceinline__ void block_reduce2(float& s, float& s2, float* sh) {
#pragma unroll
    for (int o = 16; o > 0; o >>= 1) {
        s += __shfl_down_sync(0xFFFFFFFFu, s, o);
        s2 += __shfl_down_sync(0xFFFFFFFFu, s2, o);
    }
    int warp = threadIdx.x >> 5, lane = threadIdx.x & 31;
    if (lane == 0) { sh[warp * 2] = s; sh[warp * 2 + 1] = s2; }
    __syncthreads();
    float ts = 0.f, ts2 = 0.f;
#pragma unroll
    for (int w = 0; w < 8; w++) { ts += sh[w * 2]; ts2 += sh[w * 2 + 1]; }
    s = ts; s2 = ts2;
    __syncthreads();
}

__global__ void ln_res_ln_kernel(bf16* __restrict__ vhi, bf16* __restrict__ vlo,
                                 const float* __restrict__ t) {
    __shared__ float sh[16];
    int row = blockIdx.x;
    int tid = threadIdx.x;
    const float4 tv = ((const float4*)(t + (size_t)row * Dd))[tid];
    uint2 vhu = ((const uint2*)(vhi + (size_t)row * Dd))[tid];
    uint2 vlu = ((const uint2*)(vlo + (size_t)row * Dd))[tid];
    const bf16* vhp = (const bf16*)&vhu;
    const bf16* vlp = (const bf16*)&vlu;

    float s = tv.x + tv.y + tv.z + tv.w;
    float s2 = tv.x * tv.x + tv.y * tv.y + tv.z * tv.z + tv.w * tv.w;
    block_reduce2(s, s2, sh);
    float m = s * (1.0f / Dd);
    float inv = rsqrtf(s2 * (1.0f / Dd) - m * m + LN_EPS);

    float u[4];
    u[0] = (__bfloat162float(vhp[0]) + __bfloat162float(vlp[0])) + (tv.x - m) * inv;
    u[1] = (__bfloat162float(vhp[1]) + __bfloat162float(vlp[1])) + (tv.y - m) * inv;
    u[2] = (__bfloat162float(vhp[2]) + __bfloat162float(vlp[2])) + (tv.z - m) * inv;
    u[3] = (__bfloat162float(vhp[3]) + __bfloat162float(vlp[3])) + (tv.w - m) * inv;

    s = u[0] + u[1] + u[2] + u[3];
    s2 = u[0] * u[0] + u[1] * u[1] + u[2] * u[2] + u[3] * u[3];
    block_reduce2(s, s2, sh);
    m = s * (1.0f / Dd);
    inv = rsqrtf(s2 * (1.0f / Dd) - m * m + LN_EPS);

    bf16 h[4], l[4];
#pragma unroll
    for (int q = 0; q < 4; q++) bsplit((u[q] - m) * inv, h[q], l[q]);
    ((uint2*)(vhi + (size_t)row * Dd))[tid] = *(uint2*)h;
    ((uint2*)(vlo + (size_t)row * Dd))[tid] = *(uint2*)l;
}

// ---------------- cp.async helpers ------------------------------------------
__device__ __forceinline__ void cpa16(bf16* s, const bf16* g) {
    asm volatile("cp.async.cg.shared.global [%0],[%1],16;\n" ::
                 "r"((unsigned)__cvta_generic_to_shared(s)), "l"(g));
}
__device__ __forceinline__ void cpa_commit() {
    asm volatile("cp.async.commit_group;\n");
}

// ---------------- 3xBF16 split GEMM, 128x128x32 tile -------------------------
// C = op(A) @ B; A,B bf16 (hi,lo) pairs; fp32 acc; terms AhiBhi+AhiBlo+AloBhi.
constexpr int BM = 128, BN = 128, BK = 32;
enum { EPI_NONE = 0, EPI_RELU = 1, EPI_RELU_MUL = 2 };

constexpr int LDA_NT = BK + 8;   // 40
constexpr int LDA_T  = BM + 8;   // 136
constexpr int LDB    = BN + 8;   // 136
constexpr int SA_NT = BM * LDA_NT;  // 5120
constexpr int SA_T  = BK * LDA_T;   // 4352
constexpr int SBn   = BK * LDB;     // 4352

constexpr int SMEM_NT_BYTES = 2 * (2 * SA_NT + 2 * SBn) * 2;  // 75776
constexpr int SMEM_T_BYTES  = 2 * (2 * SA_T + 2 * SBn) * 2;   // 69632

template <bool TRANSA, int EPI, bool WLO>
__global__ void __launch_bounds__(256, 2)
gemm_bf16x3(const bf16* __restrict__ Ahi, const bf16* __restrict__ Alo,
            const bf16* __restrict__ Bhi, const bf16* __restrict__ Blo,
            float* __restrict__ Cf, bf16* __restrict__ Chi, bf16* __restrict__ Clo,
            const bf16* __restrict__ AuxHi, const bf16* __restrict__ AuxLo,
            int M, int Ncol, int K, long sA, long sB, long sC) {
    extern __shared__ bf16 smem[];
    constexpr int SA = TRANSA ? SA_T : SA_NT;
    constexpr int STAGE = 2 * SA + 2 * SBn;

    const int bz = blockIdx.z;
    Ahi += (long)bz * sA;
    Alo += (long)bz * sA;
    Bhi += (long)bz * sB;
    Blo += (long)bz * sB;

    const int rowBase = blockIdx.y * BM;
    const int colBase = blockIdx.x * BN;
    const int tid = threadIdx.x;
    const int warpId = tid >> 5;
    const int lane = tid & 31;
    const int wr = warpId & 3;   // 0..3 -> rows wr*32
    const int wc = warpId >> 2;  // 0..1 -> cols wc*64

    const int lda = TRANSA ? M : K;
    const int ldb = Ncol;
    const int ldc = Ncol;

    // global->smem index split (all tiles are 128x32 or 32x128 = 4096 elems)
    const int arow = tid >> 1;        // NT: 0..127
    const int acol = (tid & 1) * 16;  // NT: 0 or 16
    const int tkr = tid >> 3;         // T/B: 0..31
    const int tmc = (tid & 7) * 16;   // T/B: 0..112

    auto loadStage = [&](int s, int kBase) {
        bf16* aH = smem + s * STAGE;
        bf16* aL = aH + SA;
        bf16* bH = aL + SA;
        bf16* bL = bH + SBn;
        if constexpr (!TRANSA) {
            const bf16* gh = Ahi + (long)(rowBase + arow) * lda + kBase + acol;
            const bf16* gl = Alo + (long)(rowBase + arow) * lda + kBase + acol;
            cpa16(aH + arow * LDA_NT + acol, gh);
            cpa16(aH + arow * LDA_NT + acol + 8, gh + 8);
            cpa16(aL + arow * LDA_NT + acol, gl);
            cpa16(aL + arow * LDA_NT + acol + 8, gl + 8);
        } else {
            const bf16* gh = Ahi + (long)(kBase + tkr) * lda + rowBase + tmc;
            const bf16* gl = Alo + (long)(kBase + tkr) * lda + rowBase + tmc;
            cpa16(aH + tkr * LDA_T + tmc, gh);
            cpa16(aH + tkr * LDA_T + tmc + 8, gh + 8);
            cpa16(aL + tkr * LDA_T + tmc, gl);
            cpa16(aL + tkr * LDA_T + tmc + 8, gl + 8);
        }
        const bf16* gbh = Bhi + (long)(kBase + tkr) * ldb + colBase + tmc;
        const bf16* gbl = Blo + (long)(kBase + tkr) * ldb + colBase + tmc;
        cpa16(bH + tkr * LDB + tmc, gbh);
        cpa16(bH + tkr * LDB + tmc + 8, gbh + 8);
        cpa16(bL + tkr * LDB + tmc, gbl);
        cpa16(bL + tkr * LDB + tmc + 8, gbl + 8);
    };

    using ALayout = typename std::conditional<TRANSA, wmma::col_major, wmma::row_major>::type;
    using AFrag = wmma::fragment<wmma::matrix_a, 16, 16, 16, bf16, ALayout>;
    using BFrag = wmma::fragment<wmma::matrix_b, 16, 16, 16, bf16, wmma::row_major>;
    using CFrag = wmma::fragment<wmma::accumulator, 16, 16, 16, float>;

    CFrag acc[2][4];
#pragma unroll
    for (int i = 0; i < 2; i++)
#pragma unroll
        for (int j = 0; j < 4; j++) wmma::fill_fragment(acc[i][j], 0.0f);

    const int KT = K / BK;

    loadStage(0, 0);
    cpa_commit();

    for (int kt = 0; kt < KT; kt++) {
        const int cur = kt & 1;
        if (kt + 1 < KT) {
            loadStage(cur ^ 1, (kt + 1) * BK);
            cpa_commit();
            asm volatile("cp.async.wait_group 1;\n");
        } else {
            asm volatile("cp.async.wait_group 0;\n");
        }
        __syncthreads();

        const bf16* aH = smem + cur * STAGE;
        const bf16* aL = aH + SA;
        const bf16* bH = aL + SA;
        const bf16* bL = bH + SBn;

#pragma unroll
        for (int kk = 0; kk < BK / 16; kk++) {
            AFrag afh[2], afl[2];
#pragma unroll
            for (int i = 0; i < 2; i++) {
                if constexpr (!TRANSA) {
                    wmma::load_matrix_sync(afh[i], aH + (wr * 32 + i * 16) * LDA_NT + kk * 16, LDA_NT);
                    wmma::load_matrix_sync(afl[i], aL + (wr * 32 + i * 16) * LDA_NT + kk * 16, LDA_NT);
                } else {
                    wmma::load_matrix_sync(afh[i], aH + (kk * 16) * LDA_T + wr * 32 + i * 16, LDA_T);
                    wmma::load_matrix_sync(afl[i], aL + (kk * 16) * LDA_T + wr * 32 + i * 16, LDA_T);
                }
            }
#pragma unroll
            for (int j = 0; j < 4; j++) {
                BFrag bfh, bfl;
                wmma::load_matrix_sync(bfh, bH + (kk * 16) * LDB + wc * 64 + j * 16, LDB);
                wmma::load_matrix_sync(bfl, bL + (kk * 16) * LDB + wc * 64 + j * 16, LDB);
#pragma unroll
                for (int i = 0; i < 2; i++) {
                    wmma::mma_sync(acc[i][j], afh[i], bfl, acc[i][j]);
                    wmma::mma_sync(acc[i][j], afl[i], bfh, acc[i][j]);
                    wmma::mma_sync(acc[i][j], afh[i], bfh, acc[i][j]);
                }
            }
        }
        __syncthreads();
    }

    // ------------- epilogue (stage each 16x16 frag through smem) -------------
    float* patch = (float*)smem + warpId * 16 * 20;
    const int rr = lane >> 1;
    const int cc = (lane & 1) * 8;
#pragma unroll
    for (int i = 0; i < 2; i++)
#pragma unroll
        for (int j = 0; j < 4; j++) {
            wmma::store_matrix_sync(patch, acc[i][j], 20, wmma::mem_row_major);
            __syncwarp();
            long gr = rowBase + wr * 32 + i * 16 + rr;
            long gc = colBase + wc * 64 + j * 16 + cc;
            float vals[8];
#pragma unroll
            for (int q = 0; q < 8; q++) vals[q] = patch[rr * 20 + cc + q];
            if constexpr (EPI == EPI_RELU) {
#pragma unroll
                for (int q = 0; q < 8; q++) vals[q] = fmaxf(vals[q], 0.0f);
            } else if constexpr (EPI == EPI_RELU_MUL) {
                uint4 xhu = *(const uint4*)(AuxHi + gr * ldc + gc);
                uint4 xlu = *(const uint4*)(AuxLo + gr * ldc + gc);
                const bf16* xh = (const bf16*)&xhu;
                const bf16* xl = (const bf16*)&xlu;
#pragma unroll
                for (int q = 0; q < 8; q++)
                    vals[q] = fmaxf(vals[q], 0.0f) *
                              (__bfloat162float(xh[q]) + __bfloat162float(xl[q]));
            }
            if constexpr (WLO) {
                bf16 h[8], l[8];
#pragma unroll
                for (int q = 0; q < 8; q++) bsplit(vals[q], h[q], l[q]);
                *(uint4*)(Chi + (long)bz * sC + gr * ldc + gc) = *(uint4*)h;
                *(uint4*)(Clo + (long)bz * sC + gr * ldc + gc) = *(uint4*)l;
            } else {
                *(float4*)(Cf + (long)bz * sC + gr * ldc + gc) =
                    make_float4(vals[0], vals[1], vals[2], vals[3]);
                *(float4*)(Cf + (long)bz * sC + gr * ldc + gc + 4) =
                    make_float4(vals[4], vals[5], vals[6], vals[7]);
            }
            __syncwarp();
        }
}

// ---------------- launch -----------------------------------------------------
extern "C" void kernel_launch(void* const* d_in, const int* in_sizes, int n_in,
                              void* d_out, int out_size) {
    const int* idx = (const int*)d_in[0];
    const float* emb = (const float*)d_in[1];
    const float* Dx = (const float*)d_in[2];
    const float* Dy = (const float*)d_in[3];
    const float* E = (const float*)d_in[4];
    const float* readout = (const float*)d_in[5];
    float* out = (float*)d_out;

    bf16 *vh, *vl, *xh, *xl, *kvh, *kvl, *ah, *al, *yh, *yl;
    bf16 *dxh, *dxl, *dyh, *dyl, *eh, *el, *rh, *rl;
    float* t;
    cudaGetSymbolAddress((void**)&vh, g_v_hi);
    cudaGetSymbolAddress((void**)&vl, g_v_lo);
    cudaGetSymbolAddress((void**)&xh, g_x_hi);
    cudaGetSymbolAddress((void**)&xl, g_x_lo);
    cudaGetSymbolAddress((void**)&kvh, g_kv_hi);
    cudaGetSymbolAddress((void**)&kvl, g_kv_lo);
    cudaGetSymbolAddress((void**)&ah, g_a_hi);
    cudaGetSymbolAddress((void**)&al, g_a_lo);
    cudaGetSymbolAddress((void**)&yh, g_y_hi);
    cudaGetSymbolAddress((void**)&yl, g_y_lo);
    cudaGetSymbolAddress((void**)&t, g_t);
    cudaGetSymbolAddress((void**)&dxh, g_Dx_hi);
    cudaGetSymbolAddress((void**)&dxl, g_Dx_lo);
    cudaGetSymbolAddress((void**)&dyh, g_Dy_hi);
    cudaGetSymbolAddress((void**)&dyl, g_Dy_lo);
    cudaGetSymbolAddress((void**)&eh, g_E_hi);
    cudaGetSymbolAddress((void**)&el, g_E_lo);
    cudaGetSymbolAddress((void**)&rh, g_R_hi);
    cudaGetSymbolAddress((void**)&rl, g_R_lo);

    cudaFuncSetAttribute(gemm_bf16x3<false, EPI_RELU, true>,
                         cudaFuncAttributeMaxDynamicSharedMemorySize, SMEM_NT_BYTES);
    cudaFuncSetAttribute(gemm_bf16x3<true, EPI_NONE, true>,
                         cudaFuncAttributeMaxDynamicSharedMemorySize, SMEM_T_BYTES);
    cudaFuncSetAttribute(gemm_bf16x3<false, EPI_NONE, true>,
                         cudaFuncAttributeMaxDynamicSharedMemorySize, SMEM_NT_BYTES);
    cudaFuncSetAttribute(gemm_bf16x3<false, EPI_RELU_MUL, true>,
                         cudaFuncAttributeMaxDynamicSharedMemorySize, SMEM_NT_BYTES);
    cudaFuncSetAttribute(gemm_bf16x3<false, EPI_NONE, false>,
                         cudaFuncAttributeMaxDynamicSharedMemorySize, SMEM_NT_BYTES);

    split_kernel<<<(Dd * Nn) / 2048, 256>>>(Dx, dxh, dxl);
    split_kernel<<<(Dd * Nn) / 2048, 256>>>(Dy, dyh, dyl);
    split_kernel<<<(Nn * Dd) / 2048, 256>>>(E, eh, el);
    split_kernel<<<(Dd * Vv) / 2048, 256>>>(readout, rh, rl);

    gather_kernel<<<BSROWS, 256>>>(idx, emb, vh, vl);

    for (int l = 0; l < NLAYERS; l++) {
        // x = relu(v @ Dx)
        gemm_bf16x3<false, EPI_RELU, true><<<dim3(Nn / BN, BSROWS / BM, 1), 256, SMEM_NT_BYTES>>>(
            vh, vl, dxh, dxl, nullptr, xh, xl, nullptr, nullptr, BSROWS, Nn, Dd, 0, 0, 0);

        // kv = x^T @ v per batch
        gemm_bf16x3<true, EPI_NONE, true><<<dim3(Dd / BN, Nn / BM, Bb), 256, SMEM_T_BYTES>>>(
            xh, xl, vh, vl, nullptr, kvh, kvl, nullptr, nullptr, Nn, Dd, Ss,
            (long)Ss * Nn, (long)Ss * Dd, (long)Nn * Dd);

        // a = x @ kv per batch
        gemm_bf16x3<false, EPI_NONE, true><<<dim3(Dd / BN, Ss / BM, Bb), 256, SMEM_NT_BYTES>>>(
            xh, xl, kvh, kvl, nullptr, ah, al, nullptr, nullptr, Ss, Dd, Nn,
            (long)Ss * Nn, (long)Nn * Dd, (long)Ss * Dd);

        // y = relu(a @ Dy) * x
        gemm_bf16x3<false, EPI_RELU_MUL, true><<<dim3(Nn / BN, BSROWS / BM, 1), 256, SMEM_NT_BYTES>>>(
            ah, al, dyh, dyl, nullptr, yh, yl, xh, xl, BSROWS, Nn, Dd, 0, 0, 0);

        // t = y @ E (fp32 out)
        gemm_bf16x3<false, EPI_NONE, false><<<dim3(Dd / BN, BSROWS / BM, 1), 256, SMEM_NT_BYTES>>>(
            yh, yl, eh, el, t, nullptr, nullptr, nullptr, nullptr, BSROWS, Dd, Nn, 0, 0, 0);

        // v = LN(v + LN(t))
        ln_res_ln_kernel<<<BSROWS, 256>>>(vh, vl, t);
    }

    // out = v @ readout (fp32, 3-term)
    gemm_bf16x3<false, EPI_NONE, false><<<dim3(Vv / BN, BSROWS / BM, 1), 256, SMEM_NT_BYTES>>>(
        vh, vl, rh, rl, out, nullptr, nullptr, nullptr, nullptr, BSROWS, Vv, Dd, 0, 0, 0);
}